// round 9
// baseline (speedup 1.0000x reference)
#include <cuda_runtime.h>

#define BATCH 4
#define C1    32
#define C2    64
#define MROWS 512
#define NB    256
#define NT    256

// Intermediates (no allocation allowed -> __device__ globals)
__device__ float g_z1[BATCH * C1 * 256];          // conv1 out: [b][ic][16x16]
__device__ __align__(16) float g_V [MROWS * C2];  // lookup @ Wv       [m][d]
__device__ float g_LT [C2 * MROWS];               // lookup transposed [k][m]
__device__ float g_w2T[512 * C2];                 // conv2 w transposed [k][oc]
__device__ unsigned g_bar;                        // monotonic grid-barrier ticket

// Software grid barrier: valid because all NB blocks are co-resident:
// __launch_bounds__(256, 2) caps regs at 128 -> 2 blocks/SM (65536 regs = RF),
// smem ~8KB/block; 256 blocks <= 148*2 = 296 capacity. Monotonic counter ->
// safe across graph replays with no reset.
__device__ __forceinline__ void gridbar() {
    __threadfence();
    __syncthreads();
    if (threadIdx.x == 0) {
        unsigned ticket = atomicAdd(&g_bar, 1u);
        unsigned target = (ticket / NB + 1u) * NB;
        while (*(volatile unsigned*)&g_bar < target) { }
        __threadfence();
    }
    __syncthreads();
}

__global__ void __launch_bounds__(NT, 2) fused_kernel(
    const float* __restrict__ x,  const float* __restrict__ w1, const float* __restrict__ b1,
    const float* __restrict__ w2, const float* __restrict__ b2,
    const float* __restrict__ lookup, const float* __restrict__ Wv,
    const float* __restrict__ Wo, float* __restrict__ out)
{
    __shared__ __align__(16) float sm[2048];   // 8 KB, phase-overlaid
    float* st  = sm + 1920;    // 64: token vector (written end of B, read in C)
    // Phase B aliases:
    float* z1v = sm;           // 512: conv2 input vector [k]
    float* zp  = sm + 512;     // 256: conv2 partials
    // Phase C aliases:
    float* ss  = sm;           // 512: softmax weights
    float* red = sm + 512;     // 32
    float* part= sm + 544;     // 256
    float* pre = sm + 800;     // 64
    float* pf  = sm + 864;     // 256

    int t    = threadIdx.x;
    int blk  = blockIdx.x;
    int lane = t & 31, warp = t >> 5;

    // ============ Phase A (uniform split across 256 blocks) =================
    //   t<128 : conv1 for 128 outputs: (b = blk>>6, oc = (blk>>1)&31,
    //           pixels (blk&1)*128 + t)
    //   t>=128: LT transpose (2 lookup rows), V (2 rows x 64 d), w2T (128 el)
    if (t < 48)   sm[t] = w1[((blk >> 1) & 31) * 48 + t];         // conv1 wts
    if (t >= 128) sm[64 + (t - 128)] = lookup[blk * 128 + (t - 128)]; // 2 rows
    __syncthreads();

    if (t < 128) {
        int b = blk >> 6, pix = (blk & 1) * 128 + t;
        int oh = pix >> 4, ow = pix & 15;
        int iw0 = ow * 2 - 1;
        float acc = b1[(blk >> 1) & 31];
        #pragma unroll
        for (int ic = 0; ic < 3; ic++) {
            const float* xp  = x + (b * 3 + ic) * 1024;
            const float* swp = sm + ic * 16;
            #pragma unroll
            for (int kh = 0; kh < 4; kh++) {
                int ih = oh * 2 - 1 + kh;
                if ((unsigned)ih < 32u) {
                    const float* xr = xp + ih * 32;
                    if (iw0 >= 0)  acc += xr[iw0]     * swp[kh * 4];
                    acc += xr[iw0 + 1] * swp[kh * 4 + 1];
                    acc += xr[iw0 + 2] * swp[kh * 4 + 2];
                    if (iw0 < 29)  acc += xr[iw0 + 3] * swp[kh * 4 + 3];
                }
            }
        }
        g_z1[blk * 128 + t] = fmaxf(acc, 0.0f);   // == (b*32+oc)*256 + pix
    } else {
        int i = t - 128;                          // 0..127
        // LT: g_LT[k][2*blk + mi] = row[mi][k]
        {
            int k = i >> 1, mi = i & 1;
            g_LT[k * 512 + blk * 2 + mi] = sm[64 + mi * 64 + k];
        }
        // w2T: coalesced read, scattered write
        {
            int j = blk * 128 + i;                // 0..32767
            g_w2T[(j & 511) * 64 + (j >> 9)] = w2[j];
        }
        // V: V[2*blk + r][d] = row_r . Wv[:,d]
        int d = i & 63;
        const float* row = sm + 64 + (i >> 6) * 64;
        float a0 = 0.f, a1 = 0.f, a2 = 0.f, a3 = 0.f;
        #pragma unroll
        for (int k = 0; k < 64; k += 4) {
            a0 += row[k]     * Wv[(k    ) * 64 + d];
            a1 += row[k + 1] * Wv[(k + 1) * 64 + d];
            a2 += row[k + 2] * Wv[(k + 2) * 64 + d];
            a3 += row[k + 3] * Wv[(k + 3) * 64 + d];
        }
        g_V[blk * 128 + i] = (a0 + a1) + (a2 + a3);
    }
    gridbar();   // the ONLY global sync

    // ============ Phase B: conv2 for this block's ONE token =================
    int b = blk >> 6, pix = blk & 63;
    {
        int r0 = 2 * (pix >> 3) - 1, c0 = 2 * (pix & 7) - 1;

        // gather conv2 input vector z1v[k], k = ic*16 + kh*4 + kw (zero-padded)
        #pragma unroll
        for (int i = t; i < 512; i += NT) {
            int ic = i >> 4, kh = (i >> 2) & 3, kw = i & 3;
            int ih = r0 + kh, iw = c0 + kw;
            float v = 0.0f;
            if ((unsigned)ih < 16u && (unsigned)iw < 16u)
                v = g_z1[(b * C1 + ic) * 256 + ih * 16 + iw];
            z1v[i] = v;
        }
        __syncthreads();

        // GEMV: thread (oc = t&63, qr = t>>6 in 0..3); coalesced 1-line loads
        {
            int oc = t & 63, qr = t >> 6;
            const float* wt = g_w2T + (qr * 128) * 64 + oc;
            const float* v0 = z1v + qr * 128;
            float a0 = 0.f, a1 = 0.f;
            #pragma unroll
            for (int j = 0; j < 128; j += 2) {
                a0 += wt[j * 64]       * v0[j];
                a1 += wt[(j + 1) * 64] * v0[j + 1];
            }
            zp[t] = a0 + a1;
        }
        __syncthreads();
        if (t < 64)
            st[t] = fmaxf((zp[t] + zp[64 + t]) + (zp[128 + t] + zp[192 + t])
                          + b2[t], 0.0f);
        __syncthreads();
    }

    // ============ Phase C: Hopfield retrieve (1 token) ======================
    // scores for memory rows t and t+256; coalesced LT; no max subtraction
    // (scores are O(0.3), exp exact-safe; softmax mathematically unchanged)
    float a0 = 0.f, a1 = 0.f, c0s = 0.f, c1s = 0.f;
    #pragma unroll
    for (int k = 0; k < 64; k += 2) {
        float s0 = st[k], s1 = st[k + 1];
        a0  += g_LT[(k    ) * 512 + t]       * s0;
        c0s += g_LT[(k    ) * 512 + t + 256] * s0;
        a1  += g_LT[(k + 1) * 512 + t]       * s1;
        c1s += g_LT[(k + 1) * 512 + t + 256] * s1;
    }
    float e0 = __expf((a0 + a1) * 0.125f);     // 1/sqrt(64)
    float e1 = __expf((c0s + c1s) * 0.125f);
    ss[t] = e0; ss[t + 256] = e1;

    // block sum
    float u = e0 + e1;
    #pragma unroll
    for (int o = 16; o; o >>= 1) u += __shfl_xor_sync(0xffffffffu, u, o);
    if (lane == 0) red[warp] = u;
    __syncthreads();                 // covers ss writes + red
    float tot = red[0];
    #pragma unroll
    for (int i = 1; i < 8; i++) tot += red[i];
    float inv = __frcp_rn(tot);

    // p@V: thread (g = t>>6 in 0..3, d = t&63); coalesced V, smem-broadcast p
    {
        int g = t >> 6, d = t & 63;
        const float* Vp = g_V + g * 8192 + d;
        const float* q  = ss + g * 128;
        float A0 = 0.f, A1 = 0.f;
        #pragma unroll
        for (int m = 0; m < 128; m += 2) {
            A0 += q[m]     * Vp[m * 64];
            A1 += q[m + 1] * Vp[(m + 1) * 64];
        }
        part[g * 64 + d] = A0 + A1;
    }
    __syncthreads();
    if (t < 64)
        pre[t] = ((part[t] + part[64 + t]) + (part[128 + t] + part[192 + t])) * inv;
    __syncthreads();

    // @Wo: thread (h = t>>6 in 0..3, e = t&63); Wo coalesced
    {
        int e = t & 63, h = t >> 6;
        float acc = 0.f;
        int d0 = h * 16;
        #pragma unroll
        for (int d = d0; d < d0 + 16; d++) acc += pre[d] * Wo[d * 64 + e];
        pf[t] = acc;
    }
    __syncthreads();
    if (t < 64)
        out[b * 4096 + t * 64 + pix] =
            (pf[t] + pf[t + 64]) + (pf[t + 128] + pf[t + 192]);
}

// ---------------------------------------------------------------------------
extern "C" void kernel_launch(void* const* d_in, const int* in_sizes, int n_in,
                              void* d_out, int out_size) {
    const float* x       = (const float*)d_in[0];
    const float* conv1_w = (const float*)d_in[1];
    const float* conv1_b = (const float*)d_in[2];
    const float* conv2_w = (const float*)d_in[3];
    const float* conv2_b = (const float*)d_in[4];
    const float* lookup  = (const float*)d_in[5];
    const float* Wv      = (const float*)d_in[6];
    const float* Wo      = (const float*)d_in[7];
    float* out = (float*)d_out;

    fused_kernel<<<NB, NT>>>(x, conv1_w, conv1_b, conv2_w, conv2_b,
                             lookup, Wv, Wo, out);
}

// round 10
// speedup vs baseline: 1.1125x; 1.1125x over previous
#include <cuda_runtime.h>

#define BATCH 4
#define C1    32
#define C2    64
#define MROWS 512
#define NB    128
#define NT    512

// Intermediates (no allocation allowed -> __device__ globals)
__device__ float g_z1[BATCH * C1 * 256];           // conv1 out: [b][ic][16x16]
__device__ __align__(16) float g_V  [MROWS * C2];  // lookup @ Wv  [m][d]
__device__ __align__(16) float g_LT4[C2 * MROWS];  // lookup as float4 [k/4][m][4]
__device__ __align__(16) float g_w2T4[512 * C2];   // conv2 w as float4 [k/4][oc][4]
__device__ unsigned g_bar;                         // monotonic grid-barrier ticket

// Software grid barrier: valid because all NB blocks are co-resident
// (128 blocks <= 148 SMs, 512 thr, 24KB smem). Monotonic counter -> safe
// across graph replays with no reset.
__device__ __forceinline__ void gridbar() {
    __threadfence();
    __syncthreads();
    if (threadIdx.x == 0) {
        unsigned ticket = atomicAdd(&g_bar, 1u);
        unsigned target = (ticket / NB + 1u) * NB;
        while (*(volatile unsigned*)&g_bar < target) { }
        __threadfence();
    }
    __syncthreads();
}

__global__ void __launch_bounds__(NT, 1) fused_kernel(
    const float* __restrict__ x,  const float* __restrict__ w1, const float* __restrict__ b1,
    const float* __restrict__ w2, const float* __restrict__ b2,
    const float* __restrict__ lookup, const float* __restrict__ Wv,
    const float* __restrict__ Wo, float* __restrict__ out)
{
    __shared__ __align__(16) float sm[5920];   // 23.7 KB, phase-overlaid
    float* st  = sm;            // 128: 2 token vectors (persist B -> C)
    // Phase A aliases:
    float* sw1 = sm + 128;      // 48:  conv1 weights for this oc
    float* slk = sm + 192;      // 256: this block's 4 lookup rows
    // Phase B aliases:
    float* z1v = sm + 128;      // 1024: conv2 input vecs [pix][512]
    float* zpA = sm + 1152;     // 512:  conv2 partials pixel0
    float* zpB = sm + 1664;     // 512:  conv2 partials pixel1
    // Phase C aliases:
    float* ss0 = sm + 128;      // 512
    float* ss1 = sm + 640;      // 512
    float* red = sm + 1152;     // 32
    float* part= sm + 1184;     // 4096: [tok][32 g][64 d]
    float* pre = sm + 5280;     // 128
    float* pf  = sm + 5408;     // 512

    int t    = threadIdx.x;
    int blk  = blockIdx.x;
    int lane = t & 31, warp = t >> 5;

    // ============ Phase A: conv1 (t<256) || LT4 + vmat + w2T4 (t>=256) ======
    if (t < 48)   sw1[t] = w1[(blk & 31) * 48 + t];
    if (t >= 256) slk[t - 256] = lookup[blk * 256 + (t - 256)];
    __syncthreads();

    if (t < 256) {
        // conv1: block -> (b, oc); thread -> output pixel. k4 s2 p1 relu.
        int b = blk >> 5, oc = blk & 31;
        int oh = t >> 4, ow = t & 15;
        int iw0 = ow * 2 - 1;
        float acc = b1[oc];
        #pragma unroll
        for (int ic = 0; ic < 3; ic++) {
            const float* xp  = x + (b * 3 + ic) * 1024;
            const float* swp = sw1 + ic * 16;
            #pragma unroll
            for (int kh = 0; kh < 4; kh++) {
                int ih = oh * 2 - 1 + kh;
                if ((unsigned)ih < 32u) {
                    const float* xr = xp + ih * 32;
                    if (iw0 >= 0)  acc += xr[iw0]     * swp[kh * 4];
                    acc += xr[iw0 + 1] * swp[kh * 4 + 1];
                    acc += xr[iw0 + 2] * swp[kh * 4 + 2];
                    if (iw0 < 29)  acc += xr[iw0 + 3] * swp[kh * 4 + 3];
                }
            }
        }
        g_z1[(b * C1 + oc) * 256 + t] = fmaxf(acc, 0.0f);
    } else {
        int i = t - 256;                              // 0..255
        // LT4: element [k>>2][4*blk+mi] component (k&3)
        {
            int k = i >> 2, mi = i & 3;
            g_LT4[(k >> 2) * 2048 + blk * 16 + mi * 4 + (k & 3)] = slk[mi * 64 + k];
        }
        // w2T4: element [k>>2][oc] component (k&3); coalesced read of w2
        {
            int j = blk * 256 + i;                    // 0..32767
            int k = j & 511, oc = j >> 9;
            g_w2T4[(k >> 2) * 256 + oc * 4 + (k & 3)] = w2[j];
        }
        // vmat: V[4blk+r][d] = row_r . Wv[:,d]
        int d = i & 63;
        const float* row = slk + (i >> 6) * 64;
        float a0 = 0.f, a1 = 0.f, a2 = 0.f, a3 = 0.f;
        #pragma unroll
        for (int k = 0; k < 64; k += 4) {
            a0 += row[k]     * Wv[(k    ) * 64 + d];
            a1 += row[k + 1] * Wv[(k + 1) * 64 + d];
            a2 += row[k + 2] * Wv[(k + 2) * 64 + d];
            a3 += row[k + 3] * Wv[(k + 3) * 64 + d];
        }
        g_V[blk * 256 + i] = (a0 + a1) + (a2 + a3);
    }
    gridbar();   // the ONLY global sync

    // ============ Phase B: conv2 for this block's 2 tokens (float4 GEMV) ====
    int b = blk >> 5, p0 = (blk & 31) * 2;    // 2 adjacent pixels, same row
    {
        int r0 = 2 * (p0 >> 3) - 1, c0 = 2 * (p0 & 7) - 1;

        // gather conv2 input vectors directly: z1v[pix][k], k = ic*16+kh*4+kw
        #pragma unroll
        for (int i = t; i < 1024; i += NT) {
            int pix = i >> 9, k = i & 511;
            int ic = k >> 4, kh = (k >> 2) & 3, kw = k & 3;
            int ih = r0 + kh, iw = c0 + kw + 2 * pix;
            float v = 0.0f;
            if ((unsigned)ih < 16u && (unsigned)iw < 16u)
                v = g_z1[(b * C1 + ic) * 256 + ih * 16 + iw];
            z1v[i] = v;
        }
        __syncthreads();

        // GEMV: thread (oc = t&63, qr = t>>6 in 0..7); 16 LDG.128 weight loads
        {
            int oc = t & 63, qr = t >> 6;
            const float4* wt4 = (const float4*)g_w2T4 + qr * 1024 + oc; // [k4][oc]
            const float4* zv4 = (const float4*)z1v;
            float a = 0.f, c = 0.f;
            #pragma unroll
            for (int k4 = 0; k4 < 16; k4++) {
                float4 w  = wt4[k4 * 64];
                float4 v0 = zv4[qr * 16 + k4];
                float4 v1 = zv4[128 + qr * 16 + k4];
                a += w.x * v0.x + w.y * v0.y + w.z * v0.z + w.w * v0.w;
                c += w.x * v1.x + w.y * v1.y + w.z * v1.z + w.w * v1.w;
            }
            zpA[t] = a;
            zpB[t] = c;
        }
        __syncthreads();
        if (t < 128) {
            int pix = t >> 6, o = t & 63;
            const float* zp = pix ? zpB : zpA;
            float s = (zp[o] + zp[64 + o]) + (zp[128 + o] + zp[192 + o])
                    + (zp[256 + o] + zp[320 + o]) + (zp[384 + o] + zp[448 + o]);
            st[pix * 64 + o] = fmaxf(s + b2[o], 0.0f);
        }
        __syncthreads();
    }

    // ============ Phase C: Hopfield retrieve (2 tokens) =====================
    // scores for memory row t (both tokens); 16 LDG.128 of LT4; no max
    // subtraction (scores are O(0.3), exp exact-safe; softmax unchanged)
    {
        const float4* LT4 = (const float4*)g_LT4;    // [k4][m]
        const float4* st4 = (const float4*)st;
        float a = 0.f, c = 0.f;
        #pragma unroll
        for (int k4 = 0; k4 < 16; k4++) {
            float4 L = LT4[k4 * 512 + t];
            float4 u = st4[k4];
            float4 v = st4[16 + k4];
            a += L.x * u.x + L.y * u.y + L.z * u.z + L.w * u.w;
            c += L.x * v.x + L.y * v.y + L.z * v.z + L.w * v.w;
        }
        ss0[t] = __expf(a * 0.125f);     // 1/sqrt(64)
        ss1[t] = __expf(c * 0.125f);
    }

    // block sum (dual)
    float u0 = ss0[t], u1 = ss1[t];
    #pragma unroll
    for (int o = 16; o; o >>= 1) {
        u0 += __shfl_xor_sync(0xffffffffu, u0, o);
        u1 += __shfl_xor_sync(0xffffffffu, u1, o);
    }
    if (lane == 0) { red[warp] = u0; red[16 + warp] = u1; }
    __syncthreads();                 // covers ss writes + red
    float tot0 = red[0], tot1 = red[16];
    #pragma unroll
    for (int i = 1; i < 16; i++) { tot0 += red[i]; tot1 += red[16 + i]; }
    float inv0 = __frcp_rn(tot0), inv1 = __frcp_rn(tot1);

    // p@V dual: thread (g = t>>4 in 0..31, q = t&15); 16 LDG.128 of V
    {
        int g = t >> 4, q = t & 15;
        const float4* V4 = (const float4*)g_V;
        float4 A  = make_float4(0.f, 0.f, 0.f, 0.f);
        float4 Bv = make_float4(0.f, 0.f, 0.f, 0.f);
        int mb = g * 16;
        #pragma unroll
        for (int m = mb; m < mb + 16; m++) {
            float4 v = V4[m * 16 + q];
            float pa = ss0[m], pb = ss1[m];
            A.x  += pa * v.x; A.y  += pa * v.y; A.z  += pa * v.z; A.w  += pa * v.w;
            Bv.x += pb * v.x; Bv.y += pb * v.y; Bv.z += pb * v.z; Bv.w += pb * v.w;
        }
        *(float4*)(part + g * 64 + q * 4)        = A;
        *(float4*)(part + 2048 + g * 64 + q * 4) = Bv;
    }
    __syncthreads();
    if (t < 128) {
        int j = t >> 6, d = t & 63;
        const float* pp = part + j * 2048;
        float s = 0.f;
        #pragma unroll
        for (int gg = 0; gg < 32; gg += 4)
            s += (pp[gg * 64 + d] + pp[(gg + 1) * 64 + d])
               + (pp[(gg + 2) * 64 + d] + pp[(gg + 3) * 64 + d]);
        pre[j * 64 + d] = s * (j ? inv1 : inv0);
    }
    __syncthreads();

    // @Wo: thread (h4 = t>>7, j = (t>>6)&1, e = t&63); Wo coalesced
    {
        int e = t & 63, j = (t >> 6) & 1, h4 = t >> 7;
        const float* pj = pre + j * 64;
        float acc = 0.f;
        int d0 = h4 * 16;
        #pragma unroll
        for (int d = d0; d < d0 + 16; d++) acc += pj[d] * Wo[d * 64 + e];
        pf[t] = acc;
    }
    __syncthreads();
    if (t < 128) {
        int j = t >> 6, e = t & 63;
        out[b * 4096 + e * 64 + p0 + j] =
            (pf[t] + pf[t + 128]) + (pf[t + 256] + pf[t + 384]);
    }
}

// ---------------------------------------------------------------------------
extern "C" void kernel_launch(void* const* d_in, const int* in_sizes, int n_in,
                              void* d_out, int out_size) {
    const float* x       = (const float*)d_in[0];
    const float* conv1_w = (const float*)d_in[1];
    const float* conv1_b = (const float*)d_in[2];
    const float* conv2_w = (const float*)d_in[3];
    const float* conv2_b = (const float*)d_in[4];
    const float* lookup  = (const float*)d_in[5];
    const float* Wv      = (const float*)d_in[6];
    const float* Wo      = (const float*)d_in[7];
    float* out = (float*)d_out;

    fused_kernel<<<NB, NT>>>(x, conv1_w, conv1_b, conv2_w, conv2_b,
                             lookup, Wv, Wo, out);
}